// round 1
// baseline (speedup 1.0000x reference)
#include <cuda_runtime.h>

#define BB 32
#define CIN 64
#define COUT 64
#define HW 32
#define KTOT 576
#define KT 64
#define NT 9

// scratch: x transposed to [ci][h][w][b] so batch is innermost (contiguous 128B rows)
__device__ float g_xt[CIN * HW * HW * BB];

__global__ void transpose_x_kernel(const float* __restrict__ x) {
    __shared__ float tile[32][33];
    int cih = blockIdx.x;             // ci*32 + h
    int lane = threadIdx.x & 31;
    int grp  = threadIdx.x >> 5;      // 0..7
    // x[b][ci][h][w] = b*65536 + cih*32 + w
    const float* src = x + (size_t)cih * 32;
#pragma unroll
    for (int i = 0; i < 4; ++i) {
        int b = grp + 8 * i;
        tile[b][lane] = src[(size_t)b * 65536 + lane];
    }
    __syncthreads();
    float* dst = g_xt + (size_t)cih * 1024;   // [w][b]
#pragma unroll
    for (int i = 0; i < 4; ++i) {
        int w = grp + 8 * i;
        dst[w * 32 + lane] = tile[lane][w];
    }
}

__global__ __launch_bounds__(128) void local2d_kernel(
    const float* __restrict__ wgt,   // [pos][co][k] contiguous per pos (k = ci*9+ki*3+kj)
    const float* __restrict__ bias,  // [co][pos]
    float* __restrict__ out)         // [b][co][pos]
{
    __shared__ float xs[KT][36];       // [k][b], padded
    __shared__ float ws[COUT][KT + 4]; // [co][k], padded (stride 68 floats, 16B-aligned)

    int pos = blockIdx.x;
    int y = pos >> 5, x = pos & 31;
    int tid = threadIdx.x;
    int by = tid & 7;    // batch group: b = by*4 .. by*4+3
    int cx = tid >> 3;   // co group: co = cx + 16j, j=0..3

    const float* wbase = wgt + (size_t)pos * (COUT * KTOT);

    unsigned long long acc[4][2] = {{0ull,0ull},{0ull,0ull},{0ull,0ull},{0ull,0ull}};

    for (int t = 0; t < NT; ++t) {
        // ---- load weight tile: 64 co x 64 k (fully coalesced 16B loads) ----
#pragma unroll
        for (int i = 0; i < 8; ++i) {
            int idx = tid + i * 128;        // 0..1023
            int co = idx >> 4, kq = idx & 15;
            float4 v = *(const float4*)(wbase + co * KTOT + t * KT + kq * 4);
            *(float4*)&ws[co][kq * 4] = v;
        }
        // ---- load x tile: 64 k x 32 b from transposed xt (contiguous per k-row) ----
#pragma unroll
        for (int i = 0; i < 4; ++i) {
            int idx = tid + i * 128;        // 0..511
            int k = idx >> 3, bq = idx & 7;
            int kg = t * KT + k;
            int ci = kg / 9;
            int r  = kg - ci * 9;
            int ki = r / 3;
            int kj = r - ki * 3;
            int iy = y + ki - 1, ix = x + kj - 1;
            float4 v = make_float4(0.f, 0.f, 0.f, 0.f);
            if ((unsigned)iy < 32u && (unsigned)ix < 32u)
                v = *(const float4*)(g_xt + ((ci * 32 + iy) * 32 + ix) * 32 + bq * 4);
            *(float4*)&xs[k][bq * 4] = v;
        }
        __syncthreads();

        // ---- compute: packed f32x2 FMAs (2x fp32 rate vs scalar FFMA) ----
#pragma unroll
        for (int kk = 0; kk < KT; ++kk) {
            ulonglong2 xv = *(const ulonglong2*)&xs[kk][by * 4]; // 4 batch vals = 2 pairs
#pragma unroll
            for (int j = 0; j < 4; ++j) {
                float wv = ws[cx + 16 * j][kk];
                unsigned long long w2;
                asm("mov.b64 %0, {%1, %1};" : "=l"(w2) : "r"(__float_as_uint(wv)));
                asm("fma.rn.f32x2 %0, %1, %2, %0;" : "+l"(acc[j][0]) : "l"(xv.x), "l"(w2));
                asm("fma.rn.f32x2 %0, %1, %2, %0;" : "+l"(acc[j][1]) : "l"(xv.y), "l"(w2));
            }
        }
        __syncthreads();
    }

    // ---- epilogue: add bias, scatter stores (coalescing candidate for later rounds) ----
    int b0 = by * 4;
#pragma unroll
    for (int j = 0; j < 4; ++j) {
        int co = cx + 16 * j;
        float bv = bias[co * 1024 + pos];
        unsigned ulo, uhi;
        asm("mov.b64 {%0, %1}, %2;" : "=r"(ulo), "=r"(uhi) : "l"(acc[j][0]));
        out[((b0 + 0) * COUT + co) * 1024 + pos] = __uint_as_float(ulo) + bv;
        out[((b0 + 1) * COUT + co) * 1024 + pos] = __uint_as_float(uhi) + bv;
        asm("mov.b64 {%0, %1}, %2;" : "=r"(ulo), "=r"(uhi) : "l"(acc[j][1]));
        out[((b0 + 2) * COUT + co) * 1024 + pos] = __uint_as_float(ulo) + bv;
        out[((b0 + 3) * COUT + co) * 1024 + pos] = __uint_as_float(uhi) + bv;
    }
}

extern "C" void kernel_launch(void* const* d_in, const int* in_sizes, int n_in,
                              void* d_out, int out_size) {
    const float* x    = (const float*)d_in[0];
    const float* wgt  = (const float*)d_in[1];
    const float* bias = (const float*)d_in[2];
    float* out = (float*)d_out;

    transpose_x_kernel<<<CIN * HW, 256>>>(x);
    local2d_kernel<<<HW * HW, 128>>>(wgt, bias, out);
}